// round 11
// baseline (speedup 1.0000x reference)
#include <cuda_runtime.h>
#include <cstdint>
#include <cstddef>

#define NN 30000
#define EE 480000
#define CC 32
#define NTT 15
#define EPSF 1e-8f

// ---------------- scratch (static device globals; no allocation) ----------------
__device__ float g_geoP[(size_t)EE * 12];  // by CSR pos p: [0..3]=(r,Y10,Y11,Y12) [4..7]=Y20..Y23 [8]=Y24
__device__ float g_v[(size_t)NN * 128];    // permuted per-node attention vectors
__device__ float g_M[2][32 * 128];         // fused Wq@Wk^T, float4-packed per (c,lane)
__device__ float g_agg[(size_t)NN * 288];  // normalized aggregates: 9 x 32 per node
__device__ float g_f0[2][NN * CC];
__device__ float g_f1[2][NN * CC * 3];
__device__ float g_f2[2][NN * CC * 5];
__device__ int   g_cnt[NN];
__device__ int   g_rowptr[NN + 1];
__device__ int   g_cursor[NN];
__device__ int   g_eid[EE];                // p -> original edge e (for edge_feat)
__device__ int   g_srcp[EE];               // p -> src node

#define FULL 0xffffffffu

// ---------------- f32x2 packed helpers ----------------
__device__ __forceinline__ unsigned long long pk2(float lo, float hi) {
    unsigned long long r;
    asm("mov.b64 %0, {%1, %2};" : "=l"(r) : "f"(lo), "f"(hi));
    return r;
}
__device__ __forceinline__ void unpk(unsigned long long v, float& lo, float& hi) {
    asm("mov.b64 {%0, %1}, %2;" : "=f"(lo), "=f"(hi) : "l"(v));
}
__device__ __forceinline__ unsigned long long dup2(float v) {
    unsigned long long r;
    asm("mov.b64 %0, {%1, %1};" : "=l"(r) : "f"(v));
    return r;
}
__device__ __forceinline__ unsigned long long fma2(unsigned long long a, unsigned long long b,
                                                   unsigned long long c) {
    unsigned long long d;
    asm("fma.rn.f32x2 %0, %1, %2, %3;" : "=l"(d) : "l"(a), "l"(b), "l"(c));
    return d;
}

// ---------------- fused attention matrices, float4-packed ----------------
__global__ void __launch_bounds__(64) mprep_kernel(const float* __restrict__ Wq,
                                                   const float* __restrict__ Wk) {
    int t = threadIdx.x;
    int l = t >> 5, lane = t & 31;
    int h = lane >> 3;
    const float* wq = Wq + l * 1024;
    const float* wk = Wk + l * 1024;
    for (int c = 0; c < 32; c++) {
#pragma unroll
        for (int k = 0; k < 4; k++) {
            int cp = (lane & 7) + 8 * k;
            float acc = 0.0f;
#pragma unroll
            for (int dh = 0; dh < 8; dh++)
                acc = fmaf(wq[c * 32 + h * 8 + dh], wk[cp * 32 + h * 8 + dh], acc);
            g_M[l][(c * 32 + lane) * 4 + k] = acc * 0.35355339059327373f;
        }
    }
}

// ---------------- degree histogram ----------------
__global__ void __launch_bounds__(256) hist_kernel(const int* __restrict__ dst) {
    int e = blockIdx.x * 256 + threadIdx.x;
    if (e >= EE) return;
    atomicAdd(&g_cnt[dst[e]], 1);
}

// ---------------- single-block scan (re-zeroes counts for graph replay) ----------------
__global__ void __launch_bounds__(1024) scan_kernel() {
    __shared__ int ssum[1024];
    const int CH = 30;
    int t = threadIdx.x;
    int start = t * CH;
    int s = 0;
    for (int i = 0; i < CH; i++) {
        int idx = start + i;
        if (idx < NN) s += g_cnt[idx];
    }
    ssum[t] = s;
    __syncthreads();
    for (int off = 1; off < 1024; off <<= 1) {
        int v = (t >= off) ? ssum[t - off] : 0;
        __syncthreads();
        ssum[t] += v;
        __syncthreads();
    }
    int run = (t == 0) ? 0 : ssum[t - 1];
    for (int i = 0; i < CH; i++) {
        int idx = start + i;
        if (idx < NN) {
            g_rowptr[idx] = run;
            g_cursor[idx] = run;
            run += g_cnt[idx];
            g_cnt[idx] = 0;
        }
    }
    if (t == 0) g_rowptr[NN] = EE;
}

// ---------------- scatter + geometry into CSR order ----------------
__global__ void __launch_bounds__(256) scatter_geo_kernel(const float* __restrict__ pos,
                                                          const int* __restrict__ src,
                                                          const int* __restrict__ dst) {
    int e = blockIdx.x * 256 + threadIdx.x;
    if (e >= EE) return;
    int s = src[e], d = dst[e];
    int p = atomicAdd(&g_cursor[d], 1);
    g_eid[p] = e;
    g_srcp[p] = s;
    float rx = pos[d * 3 + 0] - pos[s * 3 + 0];
    float ry = pos[d * 3 + 1] - pos[s * 3 + 1];
    float rz = pos[d * 3 + 2] - pos[s * 3 + 2];
    float r = sqrtf(rx * rx + ry * ry + rz * rz + EPSF);
    float inv = 1.0f / r;
    float x = rx * inv, y = ry * inv, z = rz * inv;
    float* gp = &g_geoP[(size_t)p * 12];
    *(float4*)(gp)     = make_float4(r, x, y, z);
    *(float4*)(gp + 4) = make_float4(x * y, y * z, 3.0f * z * z - 1.0f, x * z);
    gp[8] = x * x - y * y;
}

// ---------------- per-node attention vectors: v = f0 @ M (grid-stride) ----------------
__global__ void __launch_bounds__(256) vn_kernel(const float* __restrict__ Ml,
                                                 const float* __restrict__ f0src) {
    __shared__ float sM[32 * 128];
    int tid = threadIdx.x;
    for (int i = tid; i < 32 * 128; i += 256) sM[i] = Ml[i];
    __syncthreads();
    int lane = tid & 31;
    int nwarps = gridDim.x * 8;
    for (int n = blockIdx.x * 8 + (tid >> 5); n < NN; n += nwarps) {
        float f = f0src[n * CC + lane];
        float o0 = 0, o1 = 0, o2 = 0, o3 = 0;
#pragma unroll
        for (int c = 0; c < 32; c++) {
            float fc = __shfl_sync(FULL, f, c);
            float4 m = *(const float4*)&sM[(c * 32 + lane) * 4];
            o0 = fmaf(fc, m.x, o0);
            o1 = fmaf(fc, m.y, o1);
            o2 = fmaf(fc, m.z, o2);
            o3 = fmaf(fc, m.w, o3);
        }
        float* vp = &g_v[(size_t)n * 128 + lane];
        vp[0] = o0; vp[32] = o1; vp[64] = o2; vp[96] = o3;
    }
}

// ---------------- FUSED: warp-per-node edge MLP + message + online softmax aggregate ----------------
template <bool FIRST>
__global__ void __launch_bounds__(256) fused_kernel(const float* __restrict__ edge_feat,
                                                    const float* __restrict__ Wr1,
                                                    const float* __restrict__ br1,
                                                    const float* __restrict__ Wr2,
                                                    const float* __restrict__ f0src,
                                                    const float* __restrict__ f1src,
                                                    const float* __restrict__ f2src) {
    __shared__ float sWr1[33 * 32];
    __shared__ float sbr1[32];
    __shared__ float sWr2[32 * 224];
    int tid = threadIdx.x;
    for (int i = tid; i < 33 * 32; i += 256) sWr1[i] = Wr1[i];
    if (tid < 32) sbr1[tid] = br1[tid];
    for (int i = tid; i < 32 * 224; i += 256) sWr2[i] = Wr2[i];
    __syncthreads();

    int wid = tid >> 5, lane = tid & 31;
    int nwarps = gridDim.x * 8;

    for (int n = blockIdx.x * 8 + wid; n < NN; n += nwarps) {
        int beg = g_rowptr[n];
        int deg = g_rowptr[n + 1] - beg;

        const float* vp = &g_v[(size_t)n * 128 + lane];
        float v0 = vp[0], v1 = vp[32], v2 = vp[64], v3 = vp[96];

        float mx = -1e30f, den = 0.0f;
        float A0 = 0, A10 = 0, A11 = 0, A12 = 0;
        float A20 = 0, A21 = 0, A22 = 0, A23 = 0, A24 = 0;

        for (int j0 = 0; j0 < deg; j0 += 4) {
            int cnt = deg - j0; if (cnt > 4) cnt = 4;
            int p0 = beg + j0;
            int p1 = beg + j0 + ((1 < cnt) ? 1 : 0);
            int p2 = beg + j0 + ((2 < cnt) ? 2 : 0);
            int p3 = beg + j0 + ((3 < cnt) ? 3 : 0);
            int pidx[4] = {p0, p1, p2, p3};
            int e0 = g_eid[p0], e1 = g_eid[p1], e2 = g_eid[p2], e3 = g_eid[p3];

            // ---- gather phase: issue ALL loads for this batch up-front ----
            unsigned long long fp01 = pk2(edge_feat[(size_t)e0 * CC + lane],
                                          edge_feat[(size_t)e1 * CC + lane]);
            unsigned long long fp23 = pk2(edge_feat[(size_t)e2 * CC + lane],
                                          edge_feat[(size_t)e3 * CC + lane]);
            float r0 = g_geoP[(size_t)p0 * 12];
            float r1 = g_geoP[(size_t)p1 * 12];
            float r2 = g_geoP[(size_t)p2 * 12];
            float r3 = g_geoP[(size_t)p3 * 12];
            int sA = g_srcp[p0], sB = g_srcp[p1], sC = g_srcp[p2], sD = g_srcp[p3];
            int sidx[4] = {sA, sB, sC, sD};
            float pf0[4];
            float pf1[4][3];
            float pf2[4][5];
#pragma unroll
            for (int q = 0; q < 4; q++) {
                pf0[q] = f0src[(size_t)sidx[q] * CC + lane];
                if (!FIRST) {
                    const float* q1 = &f1src[(size_t)sidx[q] * 96 + lane];
                    pf1[q][0] = q1[0]; pf1[q][1] = q1[32]; pf1[q][2] = q1[64];
                    const float* q2 = &f2src[(size_t)sidx[q] * 160 + lane];
                    pf2[q][0] = q2[0];  pf2[q][1] = q2[32]; pf2[q][2] = q2[64];
                    pf2[q][3] = q2[96]; pf2[q][4] = q2[128];
                }
            }

            // ---- hidden = relu([r,feat] @ Wr1 + b) ----
            float hb = sbr1[lane];
            float w0l = sWr1[lane];
            unsigned long long h01 = pk2(fmaf(r0, w0l, hb), fmaf(r1, w0l, hb));
            unsigned long long h23 = pk2(fmaf(r2, w0l, hb), fmaf(r3, w0l, hb));
#pragma unroll
            for (int i = 0; i < 32; i++) {
                unsigned long long wd = dup2(sWr1[(i + 1) * 32 + lane]);
                h01 = fma2(__shfl_sync(FULL, fp01, i), wd, h01);
                h23 = fma2(__shfl_sync(FULL, fp23, i), wd, h23);
            }
            {
                float a, b;
                unpk(h01, a, b); h01 = pk2(fmaxf(a, 0.f), fmaxf(b, 0.f));
                unpk(h23, a, b); h23 = pk2(fmaxf(a, 0.f), fmaxf(b, 0.f));
            }

            // ---- w = hidden @ Wr2 : 7 outputs/lane x 4 edges ----
            unsigned long long W01[7], W23[7];
#pragma unroll
            for (int p = 0; p < 7; p++) { W01[p] = 0ull; W23[p] = 0ull; }
#pragma unroll
            for (int i = 0; i < 32; i++) {
                unsigned long long hs01 = __shfl_sync(FULL, h01, i);
                unsigned long long hs23 = __shfl_sync(FULL, h23, i);
                const float* wr = &sWr2[i * 224 + lane];
#pragma unroll
                for (int p = 0; p < 7; p++) {
                    unsigned long long wd = dup2(wr[p * 32]);
                    W01[p] = fma2(hs01, wd, W01[p]);
                    W23[p] = fma2(hs23, wd, W23[p]);
                }
            }

            // ---- per-edge: message, logit, online-softmax accumulate ----
#pragma unroll
            for (int pe = 0; pe < 4; pe++) {
                if (pe < cnt) {
                    float wv[7];
#pragma unroll
                    for (int p = 0; p < 7; p++) {
                        float lo, hi;
                        unpk((pe < 2) ? W01[p] : W23[p], lo, hi);
                        wv[p] = (pe & 1) ? hi : lo;
                    }
                    int p = pidx[pe];
                    float f0s = pf0[pe];
                    const float4 ga = *(const float4*)&g_geoP[(size_t)p * 12];      // r,Y10,Y11,Y12
                    const float4 gb = *(const float4*)&g_geoP[(size_t)p * 12 + 4];  // Y20..Y23
                    float Y24 = g_geoP[(size_t)p * 12 + 8];

                    float b1 = wv[3] * f0s;
                    float b2 = wv[5] * f0s;
                    float m0;
                    if (FIRST) {
                        m0 = wv[0] * f0s;
                    } else {
                        float dot1 = pf1[pe][0] * ga.y + pf1[pe][1] * ga.z + pf1[pe][2] * ga.w;
                        float dot2 = pf2[pe][0] * gb.x + pf2[pe][1] * gb.y + pf2[pe][2] * gb.z
                                   + pf2[pe][3] * gb.w + pf2[pe][4] * Y24;
                        m0 = wv[0] * f0s + wv[1] * dot1 + wv[2] * dot2;
                    }

                    // logit for this lane's head (8-lane group reduce)
                    float acc = 0.0f;
                    acc = fmaf(__shfl_sync(FULL, m0, (lane & 7)),      v0, acc);
                    acc = fmaf(__shfl_sync(FULL, m0, (lane & 7) + 8),  v1, acc);
                    acc = fmaf(__shfl_sync(FULL, m0, (lane & 7) + 16), v2, acc);
                    acc = fmaf(__shfl_sync(FULL, m0, (lane & 7) + 24), v3, acc);
                    acc += __shfl_xor_sync(FULL, acc, 4);
                    acc += __shfl_xor_sync(FULL, acc, 2);
                    acc += __shfl_xor_sync(FULL, acc, 1);
                    float lg = acc;

                    // online softmax update (per-lane, head = lane>>3)
                    float nmx = fmaxf(mx, lg);
                    float sc = __expf(mx - nmx);
                    float w = __expf(lg - nmx);
                    mx = nmx;
                    den = den * sc + w;
                    float t1 = w * b1, t2 = w * b2;
                    A0 = A0 * sc + w * m0;
                    if (FIRST) {
                        A10 = fmaf(t1, ga.y, A10 * sc);
                        A11 = fmaf(t1, ga.z, A11 * sc);
                        A12 = fmaf(t1, ga.w, A12 * sc);
                        A20 = fmaf(t2, gb.x, A20 * sc);
                        A21 = fmaf(t2, gb.y, A21 * sc);
                        A22 = fmaf(t2, gb.z, A22 * sc);
                        A23 = fmaf(t2, gb.w, A23 * sc);
                        A24 = fmaf(t2, Y24,  A24 * sc);
                    } else {
                        float t4 = w * wv[4], t6 = w * wv[6];
                        A10 = fmaf(t1, ga.y, fmaf(t4, pf1[pe][0], A10 * sc));
                        A11 = fmaf(t1, ga.z, fmaf(t4, pf1[pe][1], A11 * sc));
                        A12 = fmaf(t1, ga.w, fmaf(t4, pf1[pe][2], A12 * sc));
                        A20 = fmaf(t2, gb.x, fmaf(t6, pf2[pe][0], A20 * sc));
                        A21 = fmaf(t2, gb.y, fmaf(t6, pf2[pe][1], A21 * sc));
                        A22 = fmaf(t2, gb.z, fmaf(t6, pf2[pe][2], A22 * sc));
                        A23 = fmaf(t2, gb.w, fmaf(t6, pf2[pe][3], A23 * sc));
                        A24 = fmaf(t2, Y24,  fmaf(t6, pf2[pe][4], A24 * sc));
                    }
                }
            }
        }

        float invd = 1.0f / (den + EPSF);
        float* ag = &g_agg[(size_t)n * 288];
        ag[lane]        = A0 * invd;
        ag[32 + lane]   = A10 * invd;
        ag[64 + lane]   = A11 * invd;
        ag[96 + lane]   = A12 * invd;
        ag[128 + lane]  = A20 * invd;
        ag[160 + lane]  = A21 * invd;
        ag[192 + lane]  = A22 * invd;
        ag[224 + lane]  = A23 * invd;
        ag[256 + lane]  = A24 * invd;
    }
}

// ---------------- self-interaction + skip: streaming GEMVs (grid-stride) ----------------
__global__ void __launch_bounds__(256) selfmix_kernel(const float* __restrict__ Ws0,
                                                      const float* __restrict__ Ws1,
                                                      const float* __restrict__ Ws2,
                                                      const float* __restrict__ Wsk,
                                                      const float* __restrict__ f0old,
                                                      float* __restrict__ f0out,
                                                      float* __restrict__ f1out,
                                                      float* __restrict__ f2out) {
    __shared__ float sW0[1024], sW1[1024], sW2[1024], sWkm[1024];
    __shared__ float sAcc[8][320];
    int tid = threadIdx.x;
    for (int i = tid; i < 1024; i += 256) {
        sW0[i] = Ws0[i]; sW1[i] = Ws1[i]; sW2[i] = Ws2[i]; sWkm[i] = Wsk[i];
    }
    __syncthreads();

    int wid = tid >> 5, lane = tid & 31;
    int nwarps = gridDim.x * 8;
    for (int n = blockIdx.x * 8 + wid; n < NN; n += nwarps) {
        float* sa = sAcc[wid];
        const float* ag = &g_agg[(size_t)n * 288];
#pragma unroll
        for (int q = 0; q < 9; q++) sa[q * 32 + lane] = ag[q * 32 + lane];
        sa[288 + lane] = f0old[n * CC + lane];
        __syncwarp();

        float o0 = 0, o10 = 0, o11 = 0, o12 = 0;
        float o20 = 0, o21 = 0, o22 = 0, o23 = 0, o24 = 0;
#pragma unroll
        for (int c = 0; c < 32; c++) {
            float w0v = sW0[c * 32 + lane], wkv = sWkm[c * 32 + lane];
            float w1v = sW1[c * 32 + lane], w2v = sW2[c * 32 + lane];
            o0  = fmaf(sa[c], w0v, fmaf(sa[288 + c], wkv, o0));
            o10 = fmaf(sa[32 + c],  w1v, o10);
            o11 = fmaf(sa[64 + c],  w1v, o11);
            o12 = fmaf(sa[96 + c],  w1v, o12);
            o20 = fmaf(sa[128 + c], w2v, o20);
            o21 = fmaf(sa[160 + c], w2v, o21);
            o22 = fmaf(sa[192 + c], w2v, o22);
            o23 = fmaf(sa[224 + c], w2v, o23);
            o24 = fmaf(sa[256 + c], w2v, o24);
        }
        f0out[n * CC + lane] = o0;
        f1out[n * 96 + lane]       = o10;
        f1out[n * 96 + 32 + lane]  = o11;
        f1out[n * 96 + 64 + lane]  = o12;
        f2out[n * 160 + lane]        = o20;
        f2out[n * 160 + 32 + lane]   = o21;
        f2out[n * 160 + 64 + lane]   = o22;
        f2out[n * 160 + 96 + lane]   = o23;
        f2out[n * 160 + 128 + lane]  = o24;
        __syncwarp();
    }
}

// ---------------- final projection (grid-stride) ----------------
__global__ void __launch_bounds__(256) out_kernel(const float* __restrict__ Wout,
                                                  const float* __restrict__ Wc,
                                                  const float* __restrict__ f0,
                                                  float* __restrict__ out) {
    __shared__ float sWo[1024];
    __shared__ float sWc[32 * NTT];
    int tid = threadIdx.x;
    for (int i = tid; i < 1024; i += 256) sWo[i] = Wout[i];
    for (int i = tid; i < 32 * NTT; i += 256) sWc[i] = Wc[i];
    __syncthreads();
    int lane = tid & 31;
    int nwarps = gridDim.x * 8;
    for (int n = blockIdx.x * 8 + (tid >> 5); n < NN; n += nwarps) {
        float f = f0[n * CC + lane];
        float hs = 0.0f;
#pragma unroll
        for (int c = 0; c < 32; c++)
            hs = fmaf(__shfl_sync(FULL, f, c), sWo[c * 32 + lane], hs);
        out[n * CC + lane] = hs;
        float cs = 0.0f;
#pragma unroll
        for (int c = 0; c < 32; c++) {
            float hv = __shfl_sync(FULL, hs, c);
            float wc = (lane < NTT) ? sWc[c * NTT + lane] : 0.0f;
            cs = fmaf(hv, wc, cs);
        }
        if (lane < NTT) out[NN * CC + n * NTT + lane] = cs;
    }
}

// ---------------- host ----------------
extern "C" void kernel_launch(void* const* d_in, const int* in_sizes, int n_in,
                              void* d_out, int out_size) {
    const float* pos       = (const float*)d_in[0];
    const float* node_l0   = (const float*)d_in[1];
    const float* edge_feat = (const float*)d_in[2];
    const int*   edge_src  = (const int*)d_in[3];
    const int*   edge_dst  = (const int*)d_in[4];
    const float* Wr1       = (const float*)d_in[5];
    const float* br1       = (const float*)d_in[6];
    const float* Wr2       = (const float*)d_in[7];
    const float* Wq        = (const float*)d_in[8];
    const float* Wk        = (const float*)d_in[9];
    const float* Ws0       = (const float*)d_in[10];
    const float* Ws1       = (const float*)d_in[11];
    const float* Ws2       = (const float*)d_in[12];
    const float* Wsk       = (const float*)d_in[13];
    const float* Wout      = (const float*)d_in[14];
    const float* Wc        = (const float*)d_in[15];
    float* out = (float*)d_out;

    void *pf0, *pf1, *pf2, *pM;
    cudaGetSymbolAddress(&pf0, g_f0);
    cudaGetSymbolAddress(&pf1, g_f1);
    cudaGetSymbolAddress(&pf2, g_f2);
    cudaGetSymbolAddress(&pM, g_M);
    float* f0a = (float*)pf0;
    float* f0b = f0a + (size_t)NN * CC;
    float* f1a = (float*)pf1;
    float* f1b = f1a + (size_t)NN * CC * 3;
    float* f2a = (float*)pf2;
    float* f2b = f2a + (size_t)NN * CC * 5;
    float* M0 = (float*)pM;
    float* M1 = M0 + 32 * 128;

    mprep_kernel<<<1, 64>>>(Wq, Wk);
    hist_kernel<<<EE / 256, 256>>>(edge_dst);
    scan_kernel<<<1, 1024>>>();
    scatter_geo_kernel<<<EE / 256, 256>>>(pos, edge_src, edge_dst);

    const int FGRID = 940;   // fused: grid-stride, ~4 nodes/warp
    const int VGRID = 512;   // vn/selfmix/out: grid-stride

    // ---- layer 0 (f1 = f2 = 0) ----
    vn_kernel<<<VGRID, 256>>>(M0, node_l0);
    fused_kernel<true><<<FGRID, 256>>>(edge_feat, Wr1, br1, Wr2,
                                       node_l0, nullptr, nullptr);
    selfmix_kernel<<<VGRID, 256>>>(Ws0, Ws1, Ws2, Wsk, node_l0, f0a, f1a, f2a);

    // ---- layer 1 ----
    vn_kernel<<<VGRID, 256>>>(M1, f0a);
    fused_kernel<false><<<FGRID, 256>>>(edge_feat, Wr1 + 33 * 32, br1 + 32, Wr2 + 32 * 224,
                                        f0a, f1a, f2a);
    selfmix_kernel<<<VGRID, 256>>>(Ws0 + 1024, Ws1 + 1024, Ws2 + 1024, Wsk + 1024,
                                   f0a, f0b, f1b, f2b);

    out_kernel<<<VGRID, 256>>>(Wout, Wc, f0b, out);
}